// round 14
// baseline (speedup 1.0000x reference)
#include <cuda_runtime.h>
#include <cuda_bf16.h>
#include <cstdint>

// out = W - c * K^T (K W - V),  c = 2*0.1/(CTX*D)
// W: (4096,4096) f32, K: (512,4096) f32, V: (512,4096) f32
#define D 4096
#define CTX 512
#define SPLITK 2

// scratch (device globals -- no allocation allowed)
__device__ __align__(16) __nv_bfloat16 g_Kb[CTX * D];          // bf16 K      (4 MB)
__device__ __align__(16) __nv_bfloat16 g_Wb[(size_t)D * D];    // bf16 W      (32 MB)
__device__ __align__(16) __nv_bfloat16 g_P[CTX * D];           // bf16 (KW-V) (4 MB)
__device__ __align__(16) float g_Pf[(size_t)SPLITK * CTX * D]; // f32 partials(16 MB)

// ---------------------------------------------------------------------------
// helpers (baseline PTX only -- harness targets sm_103 without 'a')
// ---------------------------------------------------------------------------
__device__ __forceinline__ uint32_t smem_u32(const void* p) {
    uint32_t a;
    asm("{ .reg .u64 t; cvta.to.shared.u64 t, %1; cvt.u32.u64 %0, t; }" : "=r"(a) : "l"(p));
    return a;
}
#define CP16(s, g)   asm volatile("cp.async.cg.shared.global [%0], [%1], 16;" :: "r"(s), "l"(g))
#define CP_COMMIT()  asm volatile("cp.async.commit_group;" ::: "memory")
#define CP_WAIT0()   asm volatile("cp.async.wait_group 0;" ::: "memory")
#define CP_WAIT3()   asm volatile("cp.async.wait_group 3;" ::: "memory")

__device__ __forceinline__ void ldsm_x4(uint32_t (&r)[4], uint32_t a) {
    asm volatile("ldmatrix.sync.aligned.m8n8.x4.shared.b16 {%0,%1,%2,%3}, [%4];"
                 : "=r"(r[0]), "=r"(r[1]), "=r"(r[2]), "=r"(r[3]) : "r"(a));
}
__device__ __forceinline__ void ldsm_x4t(uint32_t (&r)[4], uint32_t a) {
    asm volatile("ldmatrix.sync.aligned.m8n8.x4.trans.shared.b16 {%0,%1,%2,%3}, [%4];"
                 : "=r"(r[0]), "=r"(r[1]), "=r"(r[2]), "=r"(r[3]) : "r"(a));
}
__device__ __forceinline__ void mma16816(float (&d)[4], const uint32_t (&a)[4],
                                         uint32_t b0, uint32_t b1) {
    asm volatile("mma.sync.aligned.m16n8k16.row.col.f32.bf16.bf16.f32 "
                 "{%0,%1,%2,%3}, {%4,%5,%6,%7}, {%8,%9}, {%0,%1,%2,%3};"
                 : "+f"(d[0]), "+f"(d[1]), "+f"(d[2]), "+f"(d[3])
                 : "r"(a[0]), "r"(a[1]), "r"(a[2]), "r"(a[3]), "r"(b0), "r"(b1));
}

// ---------------------------------------------------------------------------
// prep: f32 -> bf16 (8 elems/thread)
// ---------------------------------------------------------------------------
__global__ void convert_kernel(const float4* __restrict__ src, __nv_bfloat162* __restrict__ dst) {
    int i = blockIdx.x * blockDim.x + threadIdx.x;
    float4 a = src[2 * i], b = src[2 * i + 1];
    dst[4 * i + 0] = __float22bfloat162_rn(make_float2(a.x, a.y));
    dst[4 * i + 1] = __float22bfloat162_rn(make_float2(a.z, a.w));
    dst[4 * i + 2] = __float22bfloat162_rn(make_float2(b.x, b.y));
    dst[4 * i + 3] = __float22bfloat162_rn(make_float2(b.z, b.w));
}

// reduce 2 split-K partials, subtract V, emit bf16 P
__global__ void reduce_p_kernel(const float4* __restrict__ Pf, const float4* __restrict__ V,
                                __nv_bfloat162* __restrict__ P) {
    const int SL = CTX * D / 4;
    int i = blockIdx.x * blockDim.x + threadIdx.x;
    float4 s0 = Pf[i], s1 = Pf[i + SL];
    float4 v = V[i];
    float4 r;
    r.x = (s0.x + s1.x) - v.x;
    r.y = (s0.y + s1.y) - v.y;
    r.z = (s0.z + s1.z) - v.z;
    r.w = (s0.w + s1.w) - v.w;
    P[2 * i + 0] = __float22bfloat162_rn(make_float2(r.x, r.y));
    P[2 * i + 1] = __float22bfloat162_rn(make_float2(r.z, r.w));
}

// smem strides (elems): A1 tile [128 m][32 k] pad->40 ; [k][x] tiles [32][128] pad->136
#define SA1 40
#define SKX 136
#define ST1_BYTES (128 * SA1 * 2 + 32 * SKX * 2)   // 18944
#define ST2_BYTES (2 * 32 * SKX * 2)               // 17408
#define NSTAGE 5

// ---------------------------------------------------------------------------
// GEMM1 (split-K=2): Pf[z][c][n] = sum_{k in slice z} K[c][k] W[k][n]
// A = Kb [m][k] (non-trans), B = Wb [k][n] (trans).
// CTA 128x128, 128 thr, 4 warps 2x2, warp tile 64x64.  grid (32,4,2)
// ---------------------------------------------------------------------------
__global__ __launch_bounds__(128) void gemm1_mma_sk(
    const __nv_bfloat16* __restrict__ Kb, const __nv_bfloat16* __restrict__ Wb,
    float* __restrict__ Pf)
{
    extern __shared__ __align__(16) char sm[];
    const int tid = threadIdx.x, lane = tid & 31, wid = tid >> 5;
    const int j0 = blockIdx.x * 128, c0 = blockIdx.y * 128;
    const int kbase = blockIdx.z * (D / SPLITK);
    const int wm = (wid >> 1) * 64, wn = (wid & 1) * 64;

    float acc[4][8][4];
#pragma unroll
    for (int mt = 0; mt < 4; mt++)
#pragma unroll
        for (int nt = 0; nt < 8; nt++)
#pragma unroll
            for (int e = 0; e < 4; e++) acc[mt][nt][e] = 0.f;

    auto load_stage = [&](int stage, int k0) {
        char* tA = sm + stage * ST1_BYTES;
        char* tB = tA + 128 * SA1 * 2;
#pragma unroll
        for (int i = 0; i < 4; i++) {      // A: 512 chunks, 4/thread
            int c = tid + i * 128;
            int m = c >> 2, part = c & 3;
            CP16(smem_u32(tA + (m * SA1 + part * 8) * 2),
                 Kb + (size_t)(c0 + m) * D + k0 + part * 8);
        }
#pragma unroll
        for (int i = 0; i < 4; i++) {      // B: 512 chunks, 4/thread
            int c = tid + i * 128;
            int kk = c >> 4, part = c & 15;
            CP16(smem_u32(tB + (kk * SKX + part * 8) * 2),
                 Wb + (size_t)(k0 + kk) * D + j0 + part * 8);
        }
    };

    // hoisted fragment addresses (stage 0, ks 0)
    const uint32_t smb = smem_u32(sm);
    uint32_t aA[4], aB[4];
#pragma unroll
    for (int mt = 0; mt < 4; mt++) {
        int m = wm + mt * 16 + (lane & 15);
        int cc = (lane >> 4) << 3;
        aA[mt] = smb + (m * SA1 + cc) * 2;
    }
#pragma unroll
    for (int nh = 0; nh < 4; nh++) {
        int krow = (lane & 7) + ((lane >> 3) & 1) * 8;
        int ncol = wn + nh * 16 + ((lane >> 4) & 1) * 8;
        aB[nh] = smb + 128 * SA1 * 2 + (krow * SKX + ncol) * 2;
    }

    const int NIT = (D / SPLITK) / 32;  // 64
    load_stage(0, kbase); CP_COMMIT();
    load_stage(1, kbase + 32); CP_COMMIT();
    load_stage(2, kbase + 64); CP_COMMIT();
    load_stage(3, kbase + 96); CP_COMMIT();

#pragma unroll 1
    for (int it = 0; it < NIT; it++) {
        if (it < NIT - 3) CP_WAIT3(); else CP_WAIT0();
        __syncthreads();
        if (it + 4 < NIT) { load_stage((it + 4) % NSTAGE, kbase + (it + 4) * 32); CP_COMMIT(); }

        const uint32_t sb = (uint32_t)((it % NSTAGE) * ST1_BYTES);
        uint32_t af[2][4][4], bfr[2][4][4];
        // ks=0 fragments
#pragma unroll
        for (int mt = 0; mt < 4; mt++) ldsm_x4(af[0][mt], aA[mt] + sb);
#pragma unroll
        for (int nh = 0; nh < 4; nh++) ldsm_x4t(bfr[0][nh], aB[nh] + sb);
#pragma unroll
        for (int ks = 0; ks < 2; ks++) {
            if (ks == 0) {  // prefetch ks=1 fragments under ks=0 MMAs
                const uint32_t oA = sb + 32;
                const uint32_t oB = sb + 16 * SKX * 2;
#pragma unroll
                for (int mt = 0; mt < 4; mt++) ldsm_x4(af[1][mt], aA[mt] + oA);
#pragma unroll
                for (int nh = 0; nh < 4; nh++) ldsm_x4t(bfr[1][nh], aB[nh] + oB);
            }
#pragma unroll
            for (int mt = 0; mt < 4; mt++)
#pragma unroll
                for (int nt = 0; nt < 8; nt++)
                    mma16816(acc[mt][nt], af[ks][mt], bfr[ks][nt >> 1][(nt & 1) * 2],
                             bfr[ks][nt >> 1][(nt & 1) * 2 + 1]);
        }
    }

    // epilogue: f32 partial stores
    const int tq = lane >> 2, tr = lane & 3;
    float* PfZ = Pf + (size_t)blockIdx.z * CTX * D;
#pragma unroll
    for (int mt = 0; mt < 4; mt++) {
#pragma unroll
        for (int nt = 0; nt < 8; nt++) {
            int row0 = c0 + wm + mt * 16 + tq;
            int col = j0 + wn + nt * 8 + tr * 2;
            *(float2*)&PfZ[(size_t)row0 * D + col] = make_float2(acc[mt][nt][0], acc[mt][nt][1]);
            *(float2*)&PfZ[(size_t)(row0 + 8) * D + col] = make_float2(acc[mt][nt][2], acc[mt][nt][3]);
        }
    }
}

// ---------------------------------------------------------------------------
// GEMM2: out[i][j] = W[i][j] - scale * sum_c K[c][i] P[c][j]
// A = Kb [k][m] (trans), B = P [k][n] (trans).
// CTA 128x128, 128 thr, 4 warps 2x2, warp tile 64x64.  grid (32,32)
// ---------------------------------------------------------------------------
__global__ __launch_bounds__(128) void gemm2_mma(
    const __nv_bfloat16* __restrict__ Kb, const __nv_bfloat16* __restrict__ P,
    const float* __restrict__ Wmat, float* __restrict__ Out, float scale)
{
    extern __shared__ __align__(16) char sm[];
    const int tid = threadIdx.x, lane = tid & 31, wid = tid >> 5;
    const int j0 = blockIdx.x * 128, i0 = blockIdx.y * 128;
    const int wm = (wid >> 1) * 64, wn = (wid & 1) * 64;

    float acc[4][8][4];
#pragma unroll
    for (int mt = 0; mt < 4; mt++)
#pragma unroll
        for (int nt = 0; nt < 8; nt++)
#pragma unroll
            for (int e = 0; e < 4; e++) acc[mt][nt][e] = 0.f;

    auto load_stage = [&](int stage, int k0) {
        char* tA = sm + stage * ST2_BYTES;
        char* tB = tA + 32 * SKX * 2;
#pragma unroll
        for (int i = 0; i < 4; i++) {
            int c = tid + i * 128;
            int kk = c >> 4, part = c & 15;
            CP16(smem_u32(tA + (kk * SKX + part * 8) * 2),
                 Kb + (size_t)(k0 + kk) * D + i0 + part * 8);
        }
#pragma unroll
        for (int i = 0; i < 4; i++) {
            int c = tid + i * 128;
            int kk = c >> 4, part = c & 15;
            CP16(smem_u32(tB + (kk * SKX + part * 8) * 2),
                 P + (size_t)(k0 + kk) * D + j0 + part * 8);
        }
    };

    // hoisted fragment addresses (stage 0, ks 0); both operands trans
    const uint32_t smb = smem_u32(sm);
    const int krow0 = (lane & 7) + ((lane >> 3) & 1) * 8;
    uint32_t aA[4], aB[4];
#pragma unroll
    for (int mt = 0; mt < 4; mt++) {
        int mcol = wm + mt * 16 + ((lane >> 3) & 1) * 8;
        int krA = (lane & 7) + ((lane >> 4) & 1) * 8;
        aA[mt] = smb + (krA * SKX + mcol) * 2;
    }
#pragma unroll
    for (int nh = 0; nh < 4; nh++) {
        int ncol = wn + nh * 16 + ((lane >> 4) & 1) * 8;
        aB[nh] = smb + 32 * SKX * 2 + (krow0 * SKX + ncol) * 2;
    }

    const int NIT = CTX / 32;  // 16
    load_stage(0, 0); CP_COMMIT();
    load_stage(1, 32); CP_COMMIT();
    load_stage(2, 64); CP_COMMIT();
    load_stage(3, 96); CP_COMMIT();

#pragma unroll 1
    for (int it = 0; it < NIT; it++) {
        if (it < NIT - 3) CP_WAIT3(); else CP_WAIT0();
        __syncthreads();
        if (it + 4 < NIT) { load_stage((it + 4) % NSTAGE, (it + 4) * 32); CP_COMMIT(); }

        const uint32_t sb = (uint32_t)((it % NSTAGE) * ST2_BYTES);
        uint32_t af[2][4][4], bfr[2][4][4];
#pragma unroll
        for (int mt = 0; mt < 4; mt++) ldsm_x4t(af[0][mt], aA[mt] + sb);
#pragma unroll
        for (int nh = 0; nh < 4; nh++) ldsm_x4t(bfr[0][nh], aB[nh] + sb);
#pragma unroll
        for (int ks = 0; ks < 2; ks++) {
            if (ks == 0) {
                const uint32_t oK = sb + 16 * SKX * 2;
#pragma unroll
                for (int mt = 0; mt < 4; mt++) ldsm_x4t(af[1][mt], aA[mt] + oK);
#pragma unroll
                for (int nh = 0; nh < 4; nh++) ldsm_x4t(bfr[1][nh], aB[nh] + oK);
            }
#pragma unroll
            for (int mt = 0; mt < 4; mt++)
#pragma unroll
                for (int nt = 0; nt < 8; nt++)
                    mma16816(acc[mt][nt], af[ks][mt], bfr[ks][nt >> 1][(nt & 1) * 2],
                             bfr[ks][nt >> 1][(nt & 1) * 2 + 1]);
        }
    }

    // epilogue: out = W - scale * acc
    const int tq = lane >> 2, tr = lane & 3;
#pragma unroll
    for (int mt = 0; mt < 4; mt++) {
#pragma unroll
        for (int nt = 0; nt < 8; nt++) {
            int row0 = i0 + wm + mt * 16 + tq;
            int col = j0 + wn + nt * 8 + tr * 2;
            float2 w0 = *(const float2*)&Wmat[(size_t)row0 * D + col];
            float2 w1 = *(const float2*)&Wmat[(size_t)(row0 + 8) * D + col];
            float2 o0, o1;
            o0.x = w0.x - scale * acc[mt][nt][0];
            o0.y = w0.y - scale * acc[mt][nt][1];
            o1.x = w1.x - scale * acc[mt][nt][2];
            o1.y = w1.y - scale * acc[mt][nt][3];
            *(float2*)&Out[(size_t)row0 * D + col] = o0;
            *(float2*)&Out[(size_t)(row0 + 8) * D + col] = o1;
        }
    }
}

// ---------------------------------------------------------------------------
// launch
// ---------------------------------------------------------------------------
extern "C" void kernel_launch(void* const* d_in, const int* in_sizes, int n_in,
                              void* d_out, int out_size)
{
    const float* Wmat = (const float*)d_in[0];
    const float* Kmat = (const float*)d_in[1];
    const float* Vmat = (const float*)d_in[2];
    float* Out = (float*)d_out;

    __nv_bfloat16 *Kb, *Wb, *P;
    float* Pf;
    cudaGetSymbolAddress((void**)&Kb, g_Kb);
    cudaGetSymbolAddress((void**)&Wb, g_Wb);
    cudaGetSymbolAddress((void**)&P, g_P);
    cudaGetSymbolAddress((void**)&Pf, g_Pf);

    const float scale = 2.0f * 0.1f / ((float)CTX * (float)D);

    const int S1 = NSTAGE * ST1_BYTES;  // 94720
    const int S2 = NSTAGE * ST2_BYTES;  // 87040
    cudaFuncSetAttribute(gemm1_mma_sk, cudaFuncAttributeMaxDynamicSharedMemorySize, S1);
    cudaFuncSetAttribute(gemm2_mma, cudaFuncAttributeMaxDynamicSharedMemorySize, S2);

    convert_kernel<<<(CTX * D) / (256 * 8), 256>>>((const float4*)Kmat, (__nv_bfloat162*)Kb);
    convert_kernel<<<(D * (size_t)D) / (256 * 8), 256>>>((const float4*)Wmat, (__nv_bfloat162*)Wb);

    gemm1_mma_sk<<<dim3(D / 128, CTX / 128, SPLITK), 128, S1>>>(Kb, Wb, Pf);
    reduce_p_kernel<<<(CTX * D / 4) / 256, 256>>>((const float4*)Pf, (const float4*)Vmat,
                                                  (__nv_bfloat162*)P);
    gemm2_mma<<<dim3(D / 128, D / 128), 128, S2>>>(Kb, P, Wmat, Out, scale);
}

// round 15
// speedup vs baseline: 1.2389x; 1.2389x over previous
#include <cuda_runtime.h>
#include <cuda_bf16.h>
#include <cstdint>

// out = W - c * K^T (K W - V),  c = 2*0.1/(CTX*D)
// W: (4096,4096) f32, K: (512,4096) f32, V: (512,4096) f32
#define D 4096
#define CTX 512
#define SPLITK 2

// scratch (device globals -- no allocation allowed)
__device__ __align__(16) __nv_bfloat16 g_Kb[CTX * D];          // bf16 K      (4 MB)
__device__ __align__(16) __nv_bfloat16 g_Wb[(size_t)D * D];    // bf16 W      (32 MB)
__device__ __align__(16) __nv_bfloat16 g_P[CTX * D];           // bf16 (KW-V) (4 MB)
__device__ __align__(16) float g_Pf[(size_t)SPLITK * CTX * D]; // f32 partials(16 MB)

// ---------------------------------------------------------------------------
// helpers (baseline PTX only -- harness targets sm_103 without 'a')
// ---------------------------------------------------------------------------
__device__ __forceinline__ uint32_t smem_u32(const void* p) {
    uint32_t a;
    asm("{ .reg .u64 t; cvta.to.shared.u64 t, %1; cvt.u32.u64 %0, t; }" : "=r"(a) : "l"(p));
    return a;
}
#define CP16(s, g)   asm volatile("cp.async.cg.shared.global [%0], [%1], 16;" :: "r"(s), "l"(g))
#define CP_COMMIT()  asm volatile("cp.async.commit_group;" ::: "memory")
#define CP_WAIT0()   asm volatile("cp.async.wait_group 0;" ::: "memory")
#define CP_WAIT2()   asm volatile("cp.async.wait_group 2;" ::: "memory")

__device__ __forceinline__ void ldsm_x4(uint32_t (&r)[4], uint32_t a) {
    asm volatile("ldmatrix.sync.aligned.m8n8.x4.shared.b16 {%0,%1,%2,%3}, [%4];"
                 : "=r"(r[0]), "=r"(r[1]), "=r"(r[2]), "=r"(r[3]) : "r"(a));
}
__device__ __forceinline__ void ldsm_x4t(uint32_t (&r)[4], uint32_t a) {
    asm volatile("ldmatrix.sync.aligned.m8n8.x4.trans.shared.b16 {%0,%1,%2,%3}, [%4];"
                 : "=r"(r[0]), "=r"(r[1]), "=r"(r[2]), "=r"(r[3]) : "r"(a));
}
__device__ __forceinline__ void mma16816(float (&d)[4], const uint32_t (&a)[4],
                                         uint32_t b0, uint32_t b1) {
    asm volatile("mma.sync.aligned.m16n8k16.row.col.f32.bf16.bf16.f32 "
                 "{%0,%1,%2,%3}, {%4,%5,%6,%7}, {%8,%9}, {%0,%1,%2,%3};"
                 : "+f"(d[0]), "+f"(d[1]), "+f"(d[2]), "+f"(d[3])
                 : "r"(a[0]), "r"(a[1]), "r"(a[2]), "r"(a[3]), "r"(b0), "r"(b1));
}

// ---------------------------------------------------------------------------
// prep: f32 -> bf16, 16 elems/thread (2 independent float4 pair chains)
// ---------------------------------------------------------------------------
__global__ void convert_kernel(const float4* __restrict__ src, __nv_bfloat162* __restrict__ dst) {
    int i = blockIdx.x * blockDim.x + threadIdx.x;
    float4 a0 = src[4 * i + 0], b0 = src[4 * i + 1];
    float4 a1 = src[4 * i + 2], b1 = src[4 * i + 3];
    dst[8 * i + 0] = __float22bfloat162_rn(make_float2(a0.x, a0.y));
    dst[8 * i + 1] = __float22bfloat162_rn(make_float2(a0.z, a0.w));
    dst[8 * i + 2] = __float22bfloat162_rn(make_float2(b0.x, b0.y));
    dst[8 * i + 3] = __float22bfloat162_rn(make_float2(b0.z, b0.w));
    dst[8 * i + 4] = __float22bfloat162_rn(make_float2(a1.x, a1.y));
    dst[8 * i + 5] = __float22bfloat162_rn(make_float2(a1.z, a1.w));
    dst[8 * i + 6] = __float22bfloat162_rn(make_float2(b1.x, b1.y));
    dst[8 * i + 7] = __float22bfloat162_rn(make_float2(b1.z, b1.w));
}

// reduce 2 split-K partials, subtract V, emit bf16 P  (2 float4 groups/thread)
__global__ void reduce_p_kernel(const float4* __restrict__ Pf, const float4* __restrict__ V,
                                __nv_bfloat162* __restrict__ P) {
    const int SL = CTX * D / 4;
    int i0 = blockIdx.x * blockDim.x + threadIdx.x;
#pragma unroll
    for (int g = 0; g < 2; g++) {
        int i = i0 + g * (SL / 2);
        float4 s0 = Pf[i], s1 = Pf[i + SL];
        float4 v = V[i];
        float4 r;
        r.x = (s0.x + s1.x) - v.x;
        r.y = (s0.y + s1.y) - v.y;
        r.z = (s0.z + s1.z) - v.z;
        r.w = (s0.w + s1.w) - v.w;
        P[2 * i + 0] = __float22bfloat162_rn(make_float2(r.x, r.y));
        P[2 * i + 1] = __float22bfloat162_rn(make_float2(r.z, r.w));
    }
}

// smem strides (elems): A1 tile [128 m][32 k] pad->40 ; [k][x] tiles [32][128] pad->136
#define SA1 40
#define SKX 136
#define ST1_BYTES (128 * SA1 * 2 + 32 * SKX * 2)   // 18944
#define ST2_BYTES (2 * 32 * SKX * 2)               // 17408
#define NSTAGE 4

// ---------------------------------------------------------------------------
// GEMM1 (split-K=2): Pf[z][c][n] = sum_{k in slice z} K[c][k] W[k][n]
// A = Kb [m][k] (non-trans), B = Wb [k][n] (trans).
// CTA 128x128, 128 thr, 4 warps 2x2, warp tile 64x64.  grid (32,4,2)
// ---------------------------------------------------------------------------
__global__ __launch_bounds__(128, 2) void gemm1_mma_sk(
    const __nv_bfloat16* __restrict__ Kb, const __nv_bfloat16* __restrict__ Wb,
    float* __restrict__ Pf)
{
    extern __shared__ __align__(16) char sm[];
    const int tid = threadIdx.x, lane = tid & 31, wid = tid >> 5;
    const int j0 = blockIdx.x * 128, c0 = blockIdx.y * 128;
    const int kbase = blockIdx.z * (D / SPLITK);
    const int wm = (wid >> 1) * 64, wn = (wid & 1) * 64;

    float acc[4][8][4];
#pragma unroll
    for (int mt = 0; mt < 4; mt++)
#pragma unroll
        for (int nt = 0; nt < 8; nt++)
#pragma unroll
            for (int e = 0; e < 4; e++) acc[mt][nt][e] = 0.f;

    auto load_stage = [&](int stage, int k0) {
        char* tA = sm + stage * ST1_BYTES;
        char* tB = tA + 128 * SA1 * 2;
#pragma unroll
        for (int i = 0; i < 4; i++) {      // A: 512 chunks, 4/thread
            int c = tid + i * 128;
            int m = c >> 2, part = c & 3;
            CP16(smem_u32(tA + (m * SA1 + part * 8) * 2),
                 Kb + (size_t)(c0 + m) * D + k0 + part * 8);
        }
#pragma unroll
        for (int i = 0; i < 4; i++) {      // B: 512 chunks, 4/thread
            int c = tid + i * 128;
            int kk = c >> 4, part = c & 15;
            CP16(smem_u32(tB + (kk * SKX + part * 8) * 2),
                 Wb + (size_t)(k0 + kk) * D + j0 + part * 8);
        }
    };

    // hoisted fragment addresses (stage 0, ks 0)
    const uint32_t smb = smem_u32(sm);
    uint32_t aA[4], aB[4];
#pragma unroll
    for (int mt = 0; mt < 4; mt++) {
        int m = wm + mt * 16 + (lane & 15);
        int cc = (lane >> 4) << 3;
        aA[mt] = smb + (m * SA1 + cc) * 2;
    }
#pragma unroll
    for (int nh = 0; nh < 4; nh++) {
        int krow = (lane & 7) + ((lane >> 3) & 1) * 8;
        int ncol = wn + nh * 16 + ((lane >> 4) & 1) * 8;
        aB[nh] = smb + 128 * SA1 * 2 + (krow * SKX + ncol) * 2;
    }

    const int NIT = (D / SPLITK) / 32;  // 64
    load_stage(0, kbase); CP_COMMIT();
    load_stage(1, kbase + 32); CP_COMMIT();
    load_stage(2, kbase + 64); CP_COMMIT();

#pragma unroll 1
    for (int it = 0; it < NIT; it++) {
        if (it < NIT - 2) CP_WAIT2(); else CP_WAIT0();
        __syncthreads();
        if (it + 3 < NIT) { load_stage((it + 3) & (NSTAGE - 1), kbase + (it + 3) * 32); CP_COMMIT(); }

        const uint32_t sb = (uint32_t)((it & (NSTAGE - 1)) * ST1_BYTES);
#pragma unroll
        for (int ks = 0; ks < 2; ks++) {
            const uint32_t oA = sb + ks * 32;             // +16 k elems * 2B
            const uint32_t oB = sb + ks * 16 * SKX * 2;   // +16 k rows
            uint32_t af[4][4];
#pragma unroll
            for (int mt = 0; mt < 4; mt++) ldsm_x4(af[mt], aA[mt] + oA);
            uint32_t bfr[4][4];
#pragma unroll
            for (int nh = 0; nh < 4; nh++) ldsm_x4t(bfr[nh], aB[nh] + oB);
#pragma unroll
            for (int mt = 0; mt < 4; mt++)
#pragma unroll
                for (int nt = 0; nt < 8; nt++)
                    mma16816(acc[mt][nt], af[mt], bfr[nt >> 1][(nt & 1) * 2],
                             bfr[nt >> 1][(nt & 1) * 2 + 1]);
        }
    }

    // epilogue: f32 partial stores
    const int tq = lane >> 2, tr = lane & 3;
    float* PfZ = Pf + (size_t)blockIdx.z * CTX * D;
#pragma unroll
    for (int mt = 0; mt < 4; mt++) {
#pragma unroll
        for (int nt = 0; nt < 8; nt++) {
            int row0 = c0 + wm + mt * 16 + tq;
            int col = j0 + wn + nt * 8 + tr * 2;
            *(float2*)&PfZ[(size_t)row0 * D + col] = make_float2(acc[mt][nt][0], acc[mt][nt][1]);
            *(float2*)&PfZ[(size_t)(row0 + 8) * D + col] = make_float2(acc[mt][nt][2], acc[mt][nt][3]);
        }
    }
}

// ---------------------------------------------------------------------------
// GEMM2: out[i][j] = W[i][j] - scale * sum_c K[c][i] P[c][j]
// A = Kb [k][m] (trans), B = P [k][n] (trans).
// CTA 128x128, 128 thr, 4 warps 2x2, warp tile 64x64.  grid (32,32)
// ---------------------------------------------------------------------------
__global__ __launch_bounds__(128, 2) void gemm2_mma(
    const __nv_bfloat16* __restrict__ Kb, const __nv_bfloat16* __restrict__ P,
    const float* __restrict__ Wmat, float* __restrict__ Out, float scale)
{
    extern __shared__ __align__(16) char sm[];
    const int tid = threadIdx.x, lane = tid & 31, wid = tid >> 5;
    const int j0 = blockIdx.x * 128, i0 = blockIdx.y * 128;
    const int wm = (wid >> 1) * 64, wn = (wid & 1) * 64;

    float acc[4][8][4];
#pragma unroll
    for (int mt = 0; mt < 4; mt++)
#pragma unroll
        for (int nt = 0; nt < 8; nt++)
#pragma unroll
            for (int e = 0; e < 4; e++) acc[mt][nt][e] = 0.f;

    auto load_stage = [&](int stage, int k0) {
        char* tA = sm + stage * ST2_BYTES;
        char* tB = tA + 32 * SKX * 2;
#pragma unroll
        for (int i = 0; i < 4; i++) {
            int c = tid + i * 128;
            int kk = c >> 4, part = c & 15;
            CP16(smem_u32(tA + (kk * SKX + part * 8) * 2),
                 Kb + (size_t)(k0 + kk) * D + i0 + part * 8);
        }
#pragma unroll
        for (int i = 0; i < 4; i++) {
            int c = tid + i * 128;
            int kk = c >> 4, part = c & 15;
            CP16(smem_u32(tB + (kk * SKX + part * 8) * 2),
                 P + (size_t)(k0 + kk) * D + j0 + part * 8);
        }
    };

    // hoisted fragment addresses (stage 0, ks 0); both operands trans
    const uint32_t smb = smem_u32(sm);
    const int krow0 = (lane & 7) + ((lane >> 3) & 1) * 8;
    uint32_t aA[4], aB[4];
#pragma unroll
    for (int mt = 0; mt < 4; mt++) {
        int mcol = wm + mt * 16 + ((lane >> 3) & 1) * 8;
        int krA = (lane & 7) + ((lane >> 4) & 1) * 8;
        aA[mt] = smb + (krA * SKX + mcol) * 2;
    }
#pragma unroll
    for (int nh = 0; nh < 4; nh++) {
        int ncol = wn + nh * 16 + ((lane >> 4) & 1) * 8;
        aB[nh] = smb + 32 * SKX * 2 + (krow0 * SKX + ncol) * 2;
    }

    const int NIT = CTX / 32;  // 16
    load_stage(0, 0); CP_COMMIT();
    load_stage(1, 32); CP_COMMIT();
    load_stage(2, 64); CP_COMMIT();

#pragma unroll 1
    for (int it = 0; it < NIT; it++) {
        if (it < NIT - 2) CP_WAIT2(); else CP_WAIT0();
        __syncthreads();
        if (it + 3 < NIT) { load_stage((it + 3) & (NSTAGE - 1), (it + 3) * 32); CP_COMMIT(); }

        const uint32_t sb = (uint32_t)((it & (NSTAGE - 1)) * ST2_BYTES);
#pragma unroll
        for (int ks = 0; ks < 2; ks++) {
            const uint32_t oK = sb + ks * 16 * SKX * 2;
            uint32_t af[4][4];
#pragma unroll
            for (int mt = 0; mt < 4; mt++) ldsm_x4t(af[mt], aA[mt] + oK);
            uint32_t bfr[4][4];
#pragma unroll
            for (int nh = 0; nh < 4; nh++) ldsm_x4t(bfr[nh], aB[nh] + oK);
#pragma unroll
            for (int mt = 0; mt < 4; mt++)
#pragma unroll
                for (int nt = 0; nt < 8; nt++)
                    mma16816(acc[mt][nt], af[mt], bfr[nt >> 1][(nt & 1) * 2],
                             bfr[nt >> 1][(nt & 1) * 2 + 1]);
        }
    }

    // epilogue: out = W - scale * acc
    const int tq = lane >> 2, tr = lane & 3;
#pragma unroll
    for (int mt = 0; mt < 4; mt++) {
#pragma unroll
        for (int nt = 0; nt < 8; nt++) {
            int row0 = i0 + wm + mt * 16 + tq;
            int col = j0 + wn + nt * 8 + tr * 2;
            float2 w0 = *(const float2*)&Wmat[(size_t)row0 * D + col];
            float2 w1 = *(const float2*)&Wmat[(size_t)(row0 + 8) * D + col];
            float2 o0, o1;
            o0.x = w0.x - scale * acc[mt][nt][0];
            o0.y = w0.y - scale * acc[mt][nt][1];
            o1.x = w1.x - scale * acc[mt][nt][2];
            o1.y = w1.y - scale * acc[mt][nt][3];
            *(float2*)&Out[(size_t)row0 * D + col] = o0;
            *(float2*)&Out[(size_t)(row0 + 8) * D + col] = o1;
        }
    }
}

// ---------------------------------------------------------------------------
// launch
// ---------------------------------------------------------------------------
extern "C" void kernel_launch(void* const* d_in, const int* in_sizes, int n_in,
                              void* d_out, int out_size)
{
    const float* Wmat = (const float*)d_in[0];
    const float* Kmat = (const float*)d_in[1];
    const float* Vmat = (const float*)d_in[2];
    float* Out = (float*)d_out;

    __nv_bfloat16 *Kb, *Wb, *P;
    float* Pf;
    cudaGetSymbolAddress((void**)&Kb, g_Kb);
    cudaGetSymbolAddress((void**)&Wb, g_Wb);
    cudaGetSymbolAddress((void**)&P, g_P);
    cudaGetSymbolAddress((void**)&Pf, g_Pf);

    const float scale = 2.0f * 0.1f / ((float)CTX * (float)D);

    const int S1 = NSTAGE * ST1_BYTES;  // 75776
    const int S2 = NSTAGE * ST2_BYTES;  // 69632
    cudaFuncSetAttribute(gemm1_mma_sk, cudaFuncAttributeMaxDynamicSharedMemorySize, S1);
    cudaFuncSetAttribute(gemm2_mma, cudaFuncAttributeMaxDynamicSharedMemorySize, S2);

    convert_kernel<<<(CTX * D) / (256 * 16), 256>>>((const float4*)Kmat, (__nv_bfloat162*)Kb);
    convert_kernel<<<(D * (size_t)D) / (256 * 16), 256>>>((const float4*)Wmat, (__nv_bfloat162*)Wb);

    gemm1_mma_sk<<<dim3(D / 128, CTX / 128, SPLITK), 128, S1>>>(Kb, Wb, Pf);
    reduce_p_kernel<<<(CTX * D / 8) / 256, 256>>>((const float4*)Pf, (const float4*)Vmat,
                                                  (__nv_bfloat162*)P);
    gemm2_mma<<<dim3(D / 128, D / 128), 128, S2>>>(Kb, P, Wmat, Out, scale);
}